// round 16
// baseline (speedup 1.0000x reference)
#include <cuda_runtime.h>
#include <cuda_bf16.h>
#include <math.h>
#include <stdint.h>

#define T_STEPS 1024
#define NBATCH  128
#define NU      512
#define DIN     128
#define EPSF    0.01f
#define SCAN_CTAS 128
#define HSZ     (NBATCH * NU)

// z HMMA kernel smem: x B-frags hi/lo, 8192 words each
#define ZS_WORDS 8192
#define ZS_SMEM  (2 * ZS_WORDS * 4)    // 65536 B

// ---------------- device scratch --------------------------------------------
__device__ float g_z[(size_t)T_STEPS * NU * NBATCH];  // [t][j][b]
__device__ float g_h[2 * HSZ];                        // fp32 h (epilogue only)
__device__ unsigned g_hf[2][8][4096];                 // frag exchange (hi only)
__device__ unsigned g_bar_count;
__device__ volatile unsigned g_bar_phase;

__device__ __forceinline__ void mma16816(float& d0, float& d1, float& d2, float& d3,
                                         unsigned a0, unsigned a1, unsigned a2, unsigned a3,
                                         unsigned b0, unsigned b1) {
    asm volatile(
        "mma.sync.aligned.m16n8k16.row.col.f32.bf16.bf16.f32 "
        "{%0,%1,%2,%3}, {%4,%5,%6,%7}, {%8,%9}, {%0,%1,%2,%3};"
        : "+f"(d0), "+f"(d1), "+f"(d2), "+f"(d3)
        : "r"(a0), "r"(a1), "r"(a2), "r"(a3), "r"(b0), "r"(b1));
}

// ---------------- fallback grid barrier --------------------------------------
__device__ __forceinline__ void grid_barrier() {
    __syncthreads();
    if (threadIdx.x == 0) {
        unsigned ph = g_bar_phase;
        __threadfence();
        if (atomicAdd(&g_bar_count, 1u) == SCAN_CTAS - 1u) {
            atomicExch(&g_bar_count, 0u);
            __threadfence();
            g_bar_phase = ph + 1u;
        } else {
            while (g_bar_phase == ph) { __nanosleep(32); }
        }
        __threadfence();
    }
    __syncthreads();
}

// ---------------- z HMMA kernel (R15, passing) -------------------------------
__global__ void __launch_bounds__(256) z_kernel(const float* __restrict__ x,
                                                const float* __restrict__ Ew,
                                                const float* __restrict__ Eb) {
    extern __shared__ unsigned zs[];
    unsigned* xsH = zs;              // [nt16][kt8][lane32][r2]
    unsigned* xsL = zs + ZS_WORDS;
    const int t     = blockIdx.x;
    const int jhalf = blockIdx.y;
    const int tid   = threadIdx.x;
    const int w     = tid >> 5;
    const int lane  = tid & 31;

    for (int p = tid; p < 128 * 64; p += 256) {
        int b  = p >> 6;
        int kp = p & 63;
        float2 xv = *(const float2*)(x + ((size_t)b * T_STEPS + t) * DIN + kp * 2);
        __nv_bfloat162 hi = __float22bfloat162_rn(xv);
        __nv_bfloat162 lo = __float22bfloat162_rn(
            make_float2(xv.x - __low2float(hi), xv.y - __high2float(hi)));
        int idx = (((b >> 3) * 8 + (kp >> 3)) * 32 + (b & 7) * 4 + (kp & 3)) * 2 + ((kp >> 2) & 1);
        xsH[idx] = *reinterpret_cast<unsigned*>(&hi);
        xsL[idx] = *reinterpret_cast<unsigned*>(&lo);
    }

    unsigned eH[2][8][4], eL[2][8][4];
    float ebv[2][2];
    #pragma unroll
    for (int mt = 0; mt < 2; mt++) {
        const int jbase = (jhalf * 16 + w * 2 + mt) * 16;
        ebv[mt][0] = Eb[jbase + (lane >> 2)];
        ebv[mt][1] = Eb[jbase + (lane >> 2) + 8];
        #pragma unroll
        for (int kt = 0; kt < 8; kt++) {
            #pragma unroll
            for (int r = 0; r < 4; r++) {
                int j = jbase + (lane >> 2) + 8 * (r & 1);
                int k = kt * 16 + (lane & 3) * 2 + 8 * (r >> 1);
                float v0 = Ew[(size_t)k * NU + j];
                float v1 = Ew[(size_t)(k + 1) * NU + j];
                __nv_bfloat162 hi = __float22bfloat162_rn(make_float2(v0, v1));
                __nv_bfloat162 lo = __float22bfloat162_rn(
                    make_float2(v0 - __low2float(hi), v1 - __high2float(hi)));
                eH[mt][kt][r] = *reinterpret_cast<unsigned*>(&hi);
                eL[mt][kt][r] = *reinterpret_cast<unsigned*>(&lo);
            }
        }
    }
    __syncthreads();

    const int jr = lane >> 2;
    const int bc = (lane & 3) * 2;
    #pragma unroll 1
    for (int nb = 0; nb < 16; nb++) {
        float a00 = 0.f, a01 = 0.f, a02 = 0.f, a03 = 0.f;
        float a10 = 0.f, a11 = 0.f, a12 = 0.f, a13 = 0.f;
        #pragma unroll
        for (int kt = 0; kt < 8; kt++) {
            uint2 bH = *(const uint2*)&xsH[((nb * 8 + kt) * 32 + lane) * 2];
            uint2 bL = *(const uint2*)&xsL[((nb * 8 + kt) * 32 + lane) * 2];
            mma16816(a00, a01, a02, a03, eH[0][kt][0], eH[0][kt][1], eH[0][kt][2], eH[0][kt][3], bH.x, bH.y);
            mma16816(a10, a11, a12, a13, eH[1][kt][0], eH[1][kt][1], eH[1][kt][2], eH[1][kt][3], bH.x, bH.y);
            mma16816(a00, a01, a02, a03, eL[0][kt][0], eL[0][kt][1], eL[0][kt][2], eL[0][kt][3], bH.x, bH.y);
            mma16816(a10, a11, a12, a13, eL[1][kt][0], eL[1][kt][1], eL[1][kt][2], eL[1][kt][3], bH.x, bH.y);
            mma16816(a00, a01, a02, a03, eH[0][kt][0], eH[0][kt][1], eH[0][kt][2], eH[0][kt][3], bL.x, bL.y);
            mma16816(a10, a11, a12, a13, eH[1][kt][0], eH[1][kt][1], eH[1][kt][2], eH[1][kt][3], bL.x, bL.y);
        }
        int b0 = nb * 8 + bc;
        #pragma unroll
        for (int mt = 0; mt < 2; mt++) {
            int jbase = (jhalf * 16 + w * 2 + mt) * 16;
            float d0 = (mt ? a10 : a00) + ebv[mt][0];
            float d1 = (mt ? a11 : a01) + ebv[mt][0];
            float d2 = (mt ? a12 : a02) + ebv[mt][1];
            float d3 = (mt ? a13 : a03) + ebv[mt][1];
            *(float2*)(g_z + ((size_t)t * NU + jbase + jr) * NBATCH + b0)     = make_float2(d0, d1);
            *(float2*)(g_z + ((size_t)t * NU + jbase + jr + 8) * NBATCH + b0) = make_float2(d2, d3);
        }
    }
}

// ---------------- HMMA scan: R15 + stale-lo (lo refreshed on even steps) -----
template <bool CLU>
__global__ void __launch_bounds__(256, 1) scan_kernel(const float* __restrict__ Bm,
                                                      const float* __restrict__ Cm,
                                                      const float* __restrict__ Dw,
                                                      const float* __restrict__ Db,
                                                      float* __restrict__ out) {
    __shared__ unsigned hfH[4096];           // h hi frags [kt][lane][reg]
    __shared__ float    red[10 * 256];       // epilogue reduction

    const int cta  = blockIdx.x;
    const int bb   = cta >> 4;
    const int col0 = (cta & 15) * 32;
    const int tid  = threadIdx.x;
    const int w    = tid >> 5;
    const int lane = tid & 31;

    // ---- weight B-fragments (1 frag x 32 kt, hi/lo), registers --------------
    const int nv  = lane >> 2;
    const int mat = nv >> 2;
    const int jw  = col0 + w * 4 + (nv & 3);
    unsigned wH[32][2], wL[32][2];
    #pragma unroll
    for (int i = 0; i < 32; i++) {
        #pragma unroll
        for (int r = 0; r < 2; r++) {
            float v[2];
            #pragma unroll
            for (int e = 0; e < 2; e++) {
                int k = i * 16 + r * 8 + (lane & 3) * 2 + e;
                float d = (k == jw) ? 0.01f : 0.0f;
                v[e] = (mat == 0)
                     ? EPSF * (Bm[(size_t)k * NU + jw] - 0.6f * Bm[(size_t)jw * NU + k] - d)
                     : (Cm[(size_t)k * NU + jw] - 0.6f * Cm[(size_t)jw * NU + k] - d);
            }
            __nv_bfloat162 hi = __float22bfloat162_rn(make_float2(v[0], v[1]));
            float2 hf = make_float2(__low2float(hi), __high2float(hi));
            __nv_bfloat162 lo = __float22bfloat162_rn(make_float2(v[0] - hf.x, v[1] - hf.y));
            wH[i][r] = *reinterpret_cast<unsigned*>(&hi);
            wL[i][r] = *reinterpret_cast<unsigned*>(&lo);
        }
    }

    for (int i = tid; i < 4096; i += 256) hfH[i] = 0u;
    __syncthreads();

    const int m0    = lane >> 2;
    const int isW   = (lane & 3) >> 1;
    const int pbl   = m0 + isW * 8;
    const int pbg   = bb * 16 + pbl;
    const int pj0   = w * 4 + (lane & 1) * 2;
    const int pjg   = col0 + pj0;

    const int wdx = (pjg >> 4) * 128
                  + ((((pbl & 7) << 2) | ((pjg >> 1) & 3)) << 2)
                  + ((pbl >> 3) | (((pjg >> 3) & 1) << 1));

    float hold0 = 0.f, hold1 = 0.f;
    float la0 = 0.f, la1 = 0.f, lw0 = 0.f, lw1 = 0.f;   // stale lo products

    float zn0 = __ldcg(g_z + ((size_t)0 * NU + pjg) * NBATCH + pbg);
    float zn1 = __ldcg(g_z + ((size_t)0 * NU + pjg + 1) * NBATCH + pbg);

    for (int tp = 0; tp < T_STEPS; tp += 2) {
        // ================= EVEN step t = tp: hi + lo =========================
        {
            float zv0 = zn0, zv1 = zn1;
            zn0 = __ldcg(g_z + ((size_t)(tp + 1) * NU + pjg) * NBATCH + pbg);
            zn1 = __ldcg(g_z + ((size_t)(tp + 1) * NU + pjg + 1) * NBATCH + pbg);

            float hA0 = 0.f, hA1 = 0.f, hA2 = 0.f, hA3 = 0.f;
            float hB0 = 0.f, hB1 = 0.f, hB2 = 0.f, hB3 = 0.f;
            float lA0 = 0.f, lA1 = 0.f, lA2 = 0.f, lA3 = 0.f;
            float lB0 = 0.f, lB1 = 0.f, lB2 = 0.f, lB3 = 0.f;
            #pragma unroll
            for (int i = 0; i < 16; i++) {
                int k0 = i * 2, k1 = i * 2 + 1;
                uint4 a0 = *(const uint4*)&hfH[(k0 * 32 + lane) * 4];
                uint4 a1 = *(const uint4*)&hfH[(k1 * 32 + lane) * 4];
                mma16816(hA0, hA1, hA2, hA3, a0.x, a0.y, a0.z, a0.w, wH[k0][0], wH[k0][1]);
                mma16816(hB0, hB1, hB2, hB3, a1.x, a1.y, a1.z, a1.w, wH[k1][0], wH[k1][1]);
                mma16816(lA0, lA1, lA2, lA3, a0.x, a0.y, a0.z, a0.w, wL[k0][0], wL[k0][1]);
                mma16816(lB0, lB1, lB2, lB3, a1.x, a1.y, a1.z, a1.w, wL[k1][0], wL[k1][1]);
            }
            float dh0 = hA0 + hB0, dh1 = hA1 + hB1, dh2 = hA2 + hB2, dh3 = hA3 + hB3;
            float dl0 = lA0 + lB0, dl1 = lA1 + lB1, dl2 = lA2 + lB2, dl3 = lA3 + lB3;

            // exchange hi
            float sx = isW ? dh0 : dh2;
            float sy = isW ? dh1 : dh3;
            float rx = __shfl_xor_sync(0xffffffffu, sx, 2);
            float ry = __shfl_xor_sync(0xffffffffu, sy, 2);
            float a0h = isW ? rx : dh0;
            float a1h = isW ? ry : dh1;
            float w0h = isW ? dh2 : rx;
            float w1h = isW ? dh3 : ry;
            // exchange lo (save for the odd step)
            float tx = isW ? dl0 : dl2;
            float ty = isW ? dl1 : dl3;
            float ux = __shfl_xor_sync(0xffffffffu, tx, 2);
            float uy = __shfl_xor_sync(0xffffffffu, ty, 2);
            la0 = isW ? ux : dl0;
            la1 = isW ? uy : dl1;
            lw0 = isW ? dl2 : ux;
            lw1 = isW ? dl3 : uy;

            hold0 = hold0 + (a0h + la0) + EPSF * tanhf((w0h + lw0) + zv0);
            hold1 = hold1 + (a1h + la1) + EPSF * tanhf((w1h + lw1) + zv1);
            {
                __nv_bfloat162 hi = __float22bfloat162_rn(make_float2(hold0, hold1));
                g_hf[0][bb][wdx] = *reinterpret_cast<unsigned*>(&hi);
            }

            if (CLU) {
                asm volatile("barrier.cluster.arrive.aligned;" ::: "memory");
                asm volatile("barrier.cluster.wait.aligned;" ::: "memory");
            } else {
                grid_barrier();
            }

            const uint4* src = (const uint4*)&g_hf[0][bb][0];
            uint4* dst4 = (uint4*)hfH;
            #pragma unroll
            for (int it = 0; it < 4; it++) {
                int wd = it * 256 + tid;
                dst4[wd] = __ldcg(src + wd);
            }
            __syncthreads();
        }

        // ================= ODD step t = tp+1: hi only, stale lo ==============
        {
            float zv0 = zn0, zv1 = zn1;
            if (tp + 2 < T_STEPS) {
                zn0 = __ldcg(g_z + ((size_t)(tp + 2) * NU + pjg) * NBATCH + pbg);
                zn1 = __ldcg(g_z + ((size_t)(tp + 2) * NU + pjg + 1) * NBATCH + pbg);
            }

            float hA0 = 0.f, hA1 = 0.f, hA2 = 0.f, hA3 = 0.f;
            float hB0 = 0.f, hB1 = 0.f, hB2 = 0.f, hB3 = 0.f;
            #pragma unroll
            for (int i = 0; i < 16; i++) {
                int k0 = i * 2, k1 = i * 2 + 1;
                uint4 a0 = *(const uint4*)&hfH[(k0 * 32 + lane) * 4];
                uint4 a1 = *(const uint4*)&hfH[(k1 * 32 + lane) * 4];
                mma16816(hA0, hA1, hA2, hA3, a0.x, a0.y, a0.z, a0.w, wH[k0][0], wH[k0][1]);
                mma16816(hB0, hB1, hB2, hB3, a1.x, a1.y, a1.z, a1.w, wH[k1][0], wH[k1][1]);
            }
            float dh0 = hA0 + hB0, dh1 = hA1 + hB1, dh2 = hA2 + hB2, dh3 = hA3 + hB3;

            float sx = isW ? dh0 : dh2;
            float sy = isW ? dh1 : dh3;
            float rx = __shfl_xor_sync(0xffffffffu, sx, 2);
            float ry = __shfl_xor_sync(0xffffffffu, sy, 2);
            float a0h = isW ? rx : dh0;
            float a1h = isW ? ry : dh1;
            float w0h = isW ? dh2 : rx;
            float w1h = isW ? dh3 : ry;

            hold0 = hold0 + (a0h + la0) + EPSF * tanhf((w0h + lw0) + zv0);
            hold1 = hold1 + (a1h + la1) + EPSF * tanhf((w1h + lw1) + zv1);
            {
                __nv_bfloat162 hi = __float22bfloat162_rn(make_float2(hold0, hold1));
                g_hf[1][bb][wdx] = *reinterpret_cast<unsigned*>(&hi);
            }
            if (tp + 2 >= T_STEPS) {
                *(float2*)(g_h + HSZ + (size_t)pbg * NU + pjg) = make_float2(hold0, hold1);
            }

            if (CLU) {
                asm volatile("barrier.cluster.arrive.aligned;" ::: "memory");
                asm volatile("barrier.cluster.wait.aligned;" ::: "memory");
            } else {
                grid_barrier();
            }

            if (tp + 2 < T_STEPS) {
                const uint4* src = (const uint4*)&g_hf[1][bb][0];
                uint4* dst4 = (uint4*)hfH;
                #pragma unroll
                for (int it = 0; it < 4; it++) {
                    int wd = it * 256 + tid;
                    dst4[wd] = __ldcg(src + wd);
                }
            }
            __syncthreads();
        }
    }

    // ---------------- epilogue: out[b] = h_final[b] @ Dw + Db ----------------
    {
        const int b = cta;
        const float* hf = g_h + HSZ + (size_t)b * NU;
        float part[10];
        #pragma unroll
        for (int c = 0; c < 10; c++) part[c] = 0.f;
        for (int k = tid; k < NU; k += 256) {
            float hv = __ldcg(hf + k);
            #pragma unroll
            for (int c = 0; c < 10; c++) part[c] += hv * Dw[k * 10 + c];
        }
        __syncthreads();
        #pragma unroll
        for (int c = 0; c < 10; c++) red[c * 256 + tid] = part[c];
        __syncthreads();
        if (tid < 10) {
            float s = Db[tid];
            for (int i = 0; i < 256; i++) s += red[tid * 256 + i];
            out[b * 10 + tid] = s;
        }
    }
}

// ---------------- launch ------------------------------------------------------
extern "C" void kernel_launch(void* const* d_in, const int* in_sizes, int n_in,
                              void* d_out, int out_size) {
    const float* x  = (const float*)d_in[0];
    const float* B  = (const float*)d_in[1];
    const float* C  = (const float*)d_in[2];
    const float* Ew = (const float*)d_in[3];
    const float* Eb = (const float*)d_in[4];
    const float* Dw = (const float*)d_in[5];
    const float* Db = (const float*)d_in[6];
    float* outp = (float*)d_out;

    cudaFuncSetAttribute(z_kernel, cudaFuncAttributeMaxDynamicSharedMemorySize, ZS_SMEM);
    cudaFuncSetAttribute(scan_kernel<true>, cudaFuncAttributeNonPortableClusterSizeAllowed, 1);

    z_kernel<<<dim3(T_STEPS, 2), 256, ZS_SMEM>>>(x, Ew, Eb);

    cudaLaunchConfig_t cfg = {};
    cfg.gridDim  = dim3(SCAN_CTAS, 1, 1);
    cfg.blockDim = dim3(256, 1, 1);
    cfg.dynamicSmemBytes = 0;
    cfg.stream = 0;
    cudaLaunchAttribute at[1];
    at[0].id = cudaLaunchAttributeClusterDimension;
    at[0].val.clusterDim.x = 16;
    at[0].val.clusterDim.y = 1;
    at[0].val.clusterDim.z = 1;
    cfg.attrs = at;
    cfg.numAttrs = 1;

    int ncl = 0;
    cudaError_t qe = cudaOccupancyMaxActiveClusters(&ncl, scan_kernel<true>, &cfg);
    if (qe == cudaSuccess && ncl >= 1) {
        cudaLaunchKernelEx(&cfg, scan_kernel<true>, B, C, Dw, Db, outp);
    } else {
        cudaGetLastError();
        scan_kernel<false><<<SCAN_CTAS, 256>>>(B, C, Dw, Db, outp);
    }
}